// round 8
// baseline (speedup 1.0000x reference)
#include <cuda_runtime.h>
#include <cstdint>

#define IMG_D 224
#define HW (IMG_D * IMG_D)
#define NBATCH 64

#define R_TILE 14
#define HALO 3
#define WMAX (R_TILE + 2 * HALO)        // 20 rows staged
#define TILES_PER_IMG (IMG_D / R_TILE)  // 16
#define TPB 448                         // 2 sub-rows x 224 cols
#define ROWSUB 2
#define PXT (R_TILE / ROWSUB)           // 7 pixels per thread
#define PLANE_W (WMAX * IMG_D)          // 4480 floats
#define PLANE_BYTES (PLANE_W * 4)       // 17920 B
#define SMEM_BYTES (6 * PLANE_BYTES)    // 107520 B -> 2 blocks/SM

// Block = (n, 14-row tile). Stage 6 channel-plane windows (20 rows, 3-row
// halo: amplification 1.43x vs 2.0x before) with six cp.async.bulk copies +
// one mbarrier. Per k: compute 3 channels x 2 images, store immediately
// (keeps regs low for 2-block residency). C/M loads software-pipelined one
// iteration ahead. Warp-uniform ballot picks the all-smem fast path.
__global__ __launch_bounds__(TPB, 2)
void view_morph8_kernel(
    const float* __restrict__ im1,
    const float* __restrict__ im2,
    const float* __restrict__ C,
    const float* __restrict__ M1,
    const float* __restrict__ M2,
    float* __restrict__ out)
{
    extern __shared__ float sp[];
    __shared__ alignas(8) uint64_t mbar_storage;

    int blk = blockIdx.x;
    int n = blk / TILES_PER_IMG;
    int tile = blk - n * TILES_PER_IMG;
    int r0 = tile * R_TILE;

    int wl = max(0, r0 - HALO);
    int wh = min(IMG_D - 1, r0 + R_TILE - 1 + HALO);
    int wc = wh - wl + 1;

    int tid = threadIdx.x;
    int col = tid % IMG_D;
    int rsub = tid / IMG_D;

    const float* b1 = im1 + (size_t)n * 3 * HW;
    const float* b2 = im2 + (size_t)n * 3 * HW;

    uint32_t mbar = (uint32_t)__cvta_generic_to_shared(&mbar_storage);
    uint32_t spb0 = (uint32_t)__cvta_generic_to_shared(sp);

    if (tid == 0) {
        asm volatile("mbarrier.init.shared.b64 [%0], 1;"
                     :: "r"(mbar) : "memory");
    }
    __syncthreads();

    if (tid == 0) {
        uint32_t copy_bytes = (uint32_t)(wc * IMG_D * 4);
        asm volatile("mbarrier.arrive.expect_tx.shared.b64 _, [%0], %1;"
                     :: "r"(mbar), "r"(copy_bytes * 6) : "memory");
        #pragma unroll
        for (int pl = 0; pl < 6; pl++) {
            const float* src = (pl < 3 ? b1 + pl * HW : b2 + (pl - 3) * HW)
                               + wl * IMG_D;
            asm volatile(
                "cp.async.bulk.shared::cta.global.mbarrier::complete_tx::bytes"
                " [%0], [%1], %2, [%3];"
                :: "r"(spb0 + pl * PLANE_BYTES), "l"(src),
                   "r"(copy_bytes), "r"(mbar) : "memory");
        }
    }

    const float* Cn  = C  + (size_t)n * 2 * HW;
    const float* M1n = M1 + (size_t)n * HW;
    const float* M2n = M2 + (size_t)n * HW;
    float* outn = out + (size_t)n * 3 * HW;

    // prefetch k=0 C/M while TMA runs
    int p0 = (r0 + rsub) * IMG_D + col;
    float cx_c = __ldg(Cn + p0);
    float cy_c = __ldg(Cn + HW + p0);
    float m1_c = __ldg(M1n + p0);
    float m2_c = __ldg(M2n + p0);

    // wait for staged data (acquire)
    {
        uint32_t done;
        asm volatile(
            "{\n\t"
            ".reg .pred p;\n\t"
            "mbarrier.try_wait.parity.acquire.cta.shared::cta.b64 p, [%1], 0;\n\t"
            "selp.b32 %0, 1, 0, p;\n\t"
            "}"
            : "=r"(done) : "r"(mbar) : "memory");
        if (!done) {
            asm volatile(
                "{\n\t"
                ".reg .pred P1;\n\t"
                "WL_%=:\n\t"
                "mbarrier.try_wait.parity.acquire.cta.shared::cta.b64 P1, [%0], 0, 0x989680;\n\t"
                "@P1 bra.uni WD_%=;\n\t"
                "bra.uni WL_%=;\n\t"
                "WD_%=:\n\t"
                "}"
                :: "r"(mbar) : "memory");
        }
    }

    #pragma unroll
    for (int k = 0; k < PXT; k++) {
        int r = r0 + rsub + k * ROWSUB;

        float cx = cx_c, cy = cy_c, m1 = m1_c, m2 = m2_c;
        if (k + 1 < PXT) {   // pipeline next iteration's C/M
            int pn = (r + ROWSUB) * IMG_D + col;
            cx_c = __ldg(Cn + pn);
            cy_c = __ldg(Cn + HW + pn);
            m1_c = __ldg(M1n + pn);
            m2_c = __ldg(M2n + pn);
        }

        float fr = (float)r, fc = (float)col;
        float o0 = 0.f, o1 = 0.f, o2 = 0.f;

        #pragma unroll
        for (int img = 0; img < 2; img++) {
            float s = (img == 0) ? 1.0f : -1.0f;
            float m = (img == 0) ? m1 : m2;
            const float* gb = (img == 0) ? b1 : b2;
            const float* spp = sp + img * 3 * PLANE_W;

            float x = fr + s * cx;
            float y = fc + s * cy;
            x = fminf(fmaxf(x, 0.001f), (float)IMG_D - 1.001f);
            y = fminf(fmaxf(y, 0.001f), (float)IMG_D - 1.001f);

            int ixf = __float2int_rd(x);
            int ixc = __float2int_ru(x);
            int iyf = __float2int_rd(y);
            int iyc = __float2int_ru(y);

            float wxf = 1.0f - (x - (float)ixf);
            float wxc = 1.0f - ((float)ixc - x);
            float wyf = 1.0f - (y - (float)iyf);
            float wyc = 1.0f - ((float)iyc - y);

            float w00 = wxf * wyf;
            float w10 = wxc * wyf;
            float w01 = wxf * wyc;
            float w11 = wxc * wyc;

            int rf = ixf - wl;
            int rc = ixc - wl;
            bool ok = ((unsigned)rf < (unsigned)wc) &
                      ((unsigned)rc < (unsigned)wc);
            unsigned bal = __ballot_sync(0xffffffffu, ok);

            float v00[3], v10[3], v01[3], v11[3];
            if (bal == 0xffffffffu) {
                const float* smf = spp + rf * IMG_D;
                const float* smc = spp + rc * IMG_D;
                #pragma unroll
                for (int c = 0; c < 3; c++) {
                    v00[c] = smf[c * PLANE_W + iyf];
                    v01[c] = smf[c * PLANE_W + iyc];
                    v10[c] = smc[c * PLANE_W + iyf];
                    v11[c] = smc[c * PLANE_W + iyc];
                }
            } else if (ok) {
                const float* smf = spp + rf * IMG_D;
                const float* smc = spp + rc * IMG_D;
                #pragma unroll
                for (int c = 0; c < 3; c++) {
                    v00[c] = smf[c * PLANE_W + iyf];
                    v01[c] = smf[c * PLANE_W + iyc];
                    v10[c] = smc[c * PLANE_W + iyf];
                    v11[c] = smc[c * PLANE_W + iyc];
                }
            } else {
                #pragma unroll
                for (int c = 0; c < 3; c++) {
                    const float* gf = gb + c * HW + ixf * IMG_D;
                    const float* gc = gb + c * HW + ixc * IMG_D;
                    v00[c] = __ldg(gf + iyf);
                    v01[c] = __ldg(gf + iyc);
                    v10[c] = __ldg(gc + iyf);
                    v11[c] = __ldg(gc + iyc);
                }
            }

            float sv0 = w00 * v00[0] + w10 * v10[0] + w01 * v01[0] + w11 * v11[0];
            float sv1 = w00 * v00[1] + w10 * v10[1] + w01 * v01[1] + w11 * v11[1];
            float sv2 = w00 * v00[2] + w10 * v10[2] + w01 * v01[2] + w11 * v11[2];
            o0 += m * sv0;
            o1 += m * sv1;
            o2 += m * sv2;
        }

        int op = r * IMG_D + col;
        outn[op]          = o0;
        outn[HW + op]     = o1;
        outn[2 * HW + op] = o2;
    }
}

extern "C" void kernel_launch(void* const* d_in, const int* in_sizes, int n_in,
                              void* d_out, int out_size)
{
    const float* im1 = (const float*)d_in[0];
    const float* im2 = (const float*)d_in[1];
    const float* C   = (const float*)d_in[2];
    const float* M1  = (const float*)d_in[3];
    const float* M2  = (const float*)d_in[4];
    float* out = (float*)d_out;

    cudaFuncSetAttribute(view_morph8_kernel,
                         cudaFuncAttributeMaxDynamicSharedMemorySize,
                         SMEM_BYTES);

    int blocks = NBATCH * TILES_PER_IMG;  // 1024
    view_morph8_kernel<<<blocks, TPB, SMEM_BYTES>>>(im1, im2, C, M1, M2, out);
}

// round 9
// speedup vs baseline: 1.1133x; 1.1133x over previous
#include <cuda_runtime.h>
#include <cstdint>

#define IMG_D 224
#define HW (IMG_D * IMG_D)
#define NBATCH 64

#define R_TILE 8
#define HALO 4
#define WMAX (R_TILE + 2 * HALO)        // 16 rows staged
#define TILES_PER_IMG (IMG_D / R_TILE)  // 28
#define N_TILES (NBATCH * TILES_PER_IMG) // 1792
#define GRID 148                         // persistent: 1 block/SM
#define TPB 896                          // 4 sub-rows x 224 cols
#define ROWSUB 4
#define PXT (R_TILE / ROWSUB)            // 2 pixels per thread
#define PLANE_W (WMAX * IMG_D)           // 3584 floats
#define PLANE_BYTES (PLANE_W * 4)        // 14336 B
#define BUF_FLOATS (6 * PLANE_W)         // one 6-plane window
#define SMEM_BYTES (2 * 6 * PLANE_BYTES) // 172032 B (double buffered)

// Persistent block per SM, double-buffered TMA staging. Block b handles
// tiles b, b+148, ... Each tile = (n, 8-row band): 6 channel-plane windows
// (16 rows, 4-row halo) arrive via cp.async.bulk into buffer j&1 while the
// previous tile computes from the other buffer. Compute body identical to
// the proven R6 kernel (conflict-free LDS gathers + rare global fallback).

__device__ __forceinline__ void issue_stage(
    int t, int buf, uint32_t spb0, uint32_t mbar,
    const float* __restrict__ im1, const float* __restrict__ im2)
{
    int n = t / TILES_PER_IMG;
    int tile = t - n * TILES_PER_IMG;
    int r0 = tile * R_TILE;
    int wl = max(0, r0 - HALO);
    int wh = min(IMG_D - 1, r0 + R_TILE - 1 + HALO);
    int wc = wh - wl + 1;

    const float* b1 = im1 + (size_t)n * 3 * HW;
    const float* b2 = im2 + (size_t)n * 3 * HW;

    uint32_t copy_bytes = (uint32_t)(wc * IMG_D * 4);
    asm volatile("mbarrier.arrive.expect_tx.shared.b64 _, [%0], %1;"
                 :: "r"(mbar), "r"(copy_bytes * 6) : "memory");
    uint32_t dst = spb0 + (uint32_t)buf * (6 * PLANE_BYTES);
    #pragma unroll
    for (int pl = 0; pl < 6; pl++) {
        const float* src = (pl < 3 ? b1 + pl * HW : b2 + (pl - 3) * HW)
                           + wl * IMG_D;
        asm volatile(
            "cp.async.bulk.shared::cta.global.mbarrier::complete_tx::bytes"
            " [%0], [%1], %2, [%3];"
            :: "r"(dst + pl * PLANE_BYTES), "l"(src),
               "r"(copy_bytes), "r"(mbar) : "memory");
    }
}

__global__ __launch_bounds__(TPB, 1)
void view_morph9_kernel(
    const float* __restrict__ im1,
    const float* __restrict__ im2,
    const float* __restrict__ C,
    const float* __restrict__ M1,
    const float* __restrict__ M2,
    float* __restrict__ out)
{
    extern __shared__ float sp[];                    // 2 x 6-plane buffers
    __shared__ alignas(8) uint64_t mbar_storage[2];

    int tid = threadIdx.x;
    int col = tid % IMG_D;
    int rsub = tid / IMG_D;

    uint32_t mbar0 = (uint32_t)__cvta_generic_to_shared(&mbar_storage[0]);
    uint32_t mbar1 = (uint32_t)__cvta_generic_to_shared(&mbar_storage[1]);
    uint32_t spb0  = (uint32_t)__cvta_generic_to_shared(sp);

    if (tid == 0) {
        asm volatile("mbarrier.init.shared.b64 [%0], 1;" :: "r"(mbar0) : "memory");
        asm volatile("mbarrier.init.shared.b64 [%0], 1;" :: "r"(mbar1) : "memory");
    }
    __syncthreads();

    // prologue: stage first two tiles
    if (tid == 0) {
        int t0 = blockIdx.x;
        if (t0 < N_TILES)        issue_stage(t0,        0, spb0, mbar0, im1, im2);
        if (t0 + GRID < N_TILES) issue_stage(t0 + GRID, 1, spb0, mbar1, im1, im2);
    }

    for (int j = 0, t = blockIdx.x; t < N_TILES; j++, t += GRID) {
        int buf = j & 1;
        uint32_t par = (uint32_t)((j >> 1) & 1);
        uint32_t mbar = buf ? mbar1 : mbar0;

        int n = t / TILES_PER_IMG;
        int tile = t - n * TILES_PER_IMG;
        int r0 = tile * R_TILE;
        int wl = max(0, r0 - HALO);
        int wh = min(IMG_D - 1, r0 + R_TILE - 1 + HALO);
        int wc = wh - wl + 1;

        const float* b1 = im1 + (size_t)n * 3 * HW;
        const float* b2 = im2 + (size_t)n * 3 * HW;
        const float* Cn  = C  + (size_t)n * 2 * HW;
        const float* M1n = M1 + (size_t)n * HW;
        const float* M2n = M2 + (size_t)n * HW;
        const float* sbuf = sp + buf * BUF_FLOATS;

        // prefetch this tile's C/M while its TMA (and prior compute) runs
        float cx[PXT], cy[PXT], m1v[PXT], m2v[PXT];
        #pragma unroll
        for (int k = 0; k < PXT; k++) {
            int r = r0 + rsub + k * ROWSUB;
            int p = r * IMG_D + col;
            cx[k]  = __ldg(Cn + p);
            cy[k]  = __ldg(Cn + HW + p);
            m1v[k] = __ldg(M1n + p);
            m2v[k] = __ldg(M2n + p);
        }

        // wait for this buffer's data (acquire)
        {
            uint32_t done;
            asm volatile(
                "{\n\t"
                ".reg .pred p;\n\t"
                "mbarrier.try_wait.parity.acquire.cta.shared::cta.b64 p, [%1], %2;\n\t"
                "selp.b32 %0, 1, 0, p;\n\t"
                "}"
                : "=r"(done) : "r"(mbar), "r"(par) : "memory");
            if (!done) {
                asm volatile(
                    "{\n\t"
                    ".reg .pred P1;\n\t"
                    "WL_%=:\n\t"
                    "mbarrier.try_wait.parity.acquire.cta.shared::cta.b64 P1, [%0], %1, 0x989680;\n\t"
                    "@P1 bra.uni WD_%=;\n\t"
                    "bra.uni WL_%=;\n\t"
                    "WD_%=:\n\t"
                    "}"
                    :: "r"(mbar), "r"(par) : "memory");
            }
        }

        float acc[3][PXT];
        #pragma unroll
        for (int c = 0; c < 3; c++)
            #pragma unroll
            for (int k = 0; k < PXT; k++) acc[c][k] = 0.0f;

        #pragma unroll
        for (int k = 0; k < PXT; k++) {
            int r = r0 + rsub + k * ROWSUB;
            float fr = (float)r, fc = (float)col;

            #pragma unroll
            for (int img = 0; img < 2; img++) {
                float s = (img == 0) ? 1.0f : -1.0f;
                float m = (img == 0) ? m1v[k] : m2v[k];
                const float* gb = (img == 0) ? b1 : b2;
                const float* spp = sbuf + img * 3 * PLANE_W;

                float x = fr + s * cx[k];
                float y = fc + s * cy[k];
                x = fminf(fmaxf(x, 0.001f), (float)IMG_D - 1.001f);
                y = fminf(fmaxf(y, 0.001f), (float)IMG_D - 1.001f);

                int ixf = __float2int_rd(x);
                int ixc = __float2int_ru(x);
                int iyf = __float2int_rd(y);
                int iyc = __float2int_ru(y);

                float wxf = 1.0f - (x - (float)ixf);
                float wxc = 1.0f - ((float)ixc - x);
                float wyf = 1.0f - (y - (float)iyf);
                float wyc = 1.0f - ((float)iyc - y);

                float w00 = wxf * wyf;
                float w10 = wxc * wyf;
                float w01 = wxf * wyc;
                float w11 = wxc * wyc;

                int rf = ixf - wl;
                int rc = ixc - wl;
                bool ok = ((unsigned)rf < (unsigned)wc) &
                          ((unsigned)rc < (unsigned)wc);

                float v00[3], v10[3], v01[3], v11[3];
                if (ok) {
                    const float* smf = spp + rf * IMG_D;
                    const float* smc = spp + rc * IMG_D;
                    #pragma unroll
                    for (int c = 0; c < 3; c++) {
                        v00[c] = smf[c * PLANE_W + iyf];
                        v01[c] = smf[c * PLANE_W + iyc];
                        v10[c] = smc[c * PLANE_W + iyf];
                        v11[c] = smc[c * PLANE_W + iyc];
                    }
                } else {
                    #pragma unroll
                    for (int c = 0; c < 3; c++) {
                        const float* gf = gb + c * HW + ixf * IMG_D;
                        const float* gc = gb + c * HW + ixc * IMG_D;
                        v00[c] = __ldg(gf + iyf);
                        v01[c] = __ldg(gf + iyc);
                        v10[c] = __ldg(gc + iyf);
                        v11[c] = __ldg(gc + iyc);
                    }
                }

                #pragma unroll
                for (int c = 0; c < 3; c++) {
                    float sv = w00 * v00[c];
                    sv += w10 * v10[c];
                    sv += w01 * v01[c];
                    sv += w11 * v11[c];
                    acc[c][k] += m * sv;
                }
            }
        }

        float* outn = out + (size_t)n * 3 * HW;
        #pragma unroll
        for (int c = 0; c < 3; c++) {
            float* op = outn + c * HW + (r0 + rsub) * IMG_D + col;
            #pragma unroll
            for (int k = 0; k < PXT; k++)
                op[k * ROWSUB * IMG_D] = acc[c][k];
        }

        __syncthreads();   // all warps done reading sbuf
        int t2 = t + 2 * GRID;
        if (tid == 0 && t2 < N_TILES)
            issue_stage(t2, buf, spb0, mbar, im1, im2);
    }
}

extern "C" void kernel_launch(void* const* d_in, const int* in_sizes, int n_in,
                              void* d_out, int out_size)
{
    const float* im1 = (const float*)d_in[0];
    const float* im2 = (const float*)d_in[1];
    const float* C   = (const float*)d_in[2];
    const float* M1  = (const float*)d_in[3];
    const float* M2  = (const float*)d_in[4];
    float* out = (float*)d_out;

    cudaFuncSetAttribute(view_morph9_kernel,
                         cudaFuncAttributeMaxDynamicSharedMemorySize,
                         SMEM_BYTES);

    view_morph9_kernel<<<GRID, TPB, SMEM_BYTES>>>(im1, im2, C, M1, M2, out);
}

// round 10
// speedup vs baseline: 1.3153x; 1.1814x over previous
#include <cuda_runtime.h>
#include <cstdint>

#define IMG_D 224
#define HW (IMG_D * IMG_D)
#define NBATCH 64

#define R_TILE 8
#define HALO 4
#define WMAX (R_TILE + 2 * HALO)        // 16 rows staged
#define TILES_PER_IMG (IMG_D / R_TILE)  // 28
#define TPB 448                         // 2 sub-rows x 224 cols
#define ROWSUB 2
#define PXT (R_TILE / ROWSUB)           // 4 pixels per thread
#define PLANE_W (WMAX * IMG_D)          // 3584 floats
#define PLANE_BYTES (PLANE_W * 4)       // 14336 B
#define SMEM_BYTES (6 * PLANE_BYTES)    // 86016 B

// R6 structure (TMA bulk staging of 6 plane windows, one mbarrier,
// conflict-free-stride smem gathers, rare global fallback) plus ONE change:
// within each aligned 32-column group, lanes are permuted to stride-2
// columns (lane i -> (i&15)*2 + (i>>4)). This halves the probability that
// the N(0,1) y-jitter maps two lanes to the same smem bank (collision now
// needs |dy_i-dy_j|=2 instead of 1), cutting LDS bank-conflict replays.
// Global C/M/out accesses stay within one 128B line per warp -> still
// 1 wavefront each (permutation within a line is free).
__global__ __launch_bounds__(TPB)
void view_morph10_kernel(
    const float* __restrict__ im1,
    const float* __restrict__ im2,
    const float* __restrict__ C,
    const float* __restrict__ M1,
    const float* __restrict__ M2,
    float* __restrict__ out)
{
    extern __shared__ float sp[];
    __shared__ alignas(8) uint64_t mbar_storage;

    int blk = blockIdx.x;
    int n = blk / TILES_PER_IMG;
    int tile = blk - n * TILES_PER_IMG;
    int r0 = tile * R_TILE;

    int wl = max(0, r0 - HALO);
    int wh = min(IMG_D - 1, r0 + R_TILE - 1 + HALO);
    int wc = wh - wl + 1;

    int tid = threadIdx.x;
    int l = tid % IMG_D;                 // 0..223, warp-aligned 32-groups
    int rsub = tid / IMG_D;
    int lane = l & 31;
    // stride-2 permutation within the 32-column group (bijective)
    int col = (l & ~31) | (((lane & 15) << 1) | (lane >> 4));

    const float* b1 = im1 + (size_t)n * 3 * HW;
    const float* b2 = im2 + (size_t)n * 3 * HW;

    uint32_t mbar = (uint32_t)__cvta_generic_to_shared(&mbar_storage);
    uint32_t spb0 = (uint32_t)__cvta_generic_to_shared(sp);

    if (tid == 0) {
        asm volatile("mbarrier.init.shared.b64 [%0], 1;"
                     :: "r"(mbar) : "memory");
    }
    __syncthreads();

    if (tid == 0) {
        uint32_t copy_bytes = (uint32_t)(wc * IMG_D * 4);
        asm volatile("mbarrier.arrive.expect_tx.shared.b64 _, [%0], %1;"
                     :: "r"(mbar), "r"(copy_bytes * 6) : "memory");
        #pragma unroll
        for (int pl = 0; pl < 6; pl++) {
            const float* src = (pl < 3 ? b1 + pl * HW : b2 + (pl - 3) * HW)
                               + wl * IMG_D;
            asm volatile(
                "cp.async.bulk.shared::cta.global.mbarrier::complete_tx::bytes"
                " [%0], [%1], %2, [%3];"
                :: "r"(spb0 + pl * PLANE_BYTES), "l"(src),
                   "r"(copy_bytes), "r"(mbar) : "memory");
        }
    }

    // ── prefetch C/M while TMA runs ──
    const float* Cn  = C  + (size_t)n * 2 * HW;
    const float* M1n = M1 + (size_t)n * HW;
    const float* M2n = M2 + (size_t)n * HW;

    float cx[PXT], cy[PXT], m1v[PXT], m2v[PXT];
    #pragma unroll
    for (int k = 0; k < PXT; k++) {
        int r = r0 + rsub + k * ROWSUB;
        int p = r * IMG_D + col;
        cx[k]  = __ldg(Cn + p);
        cy[k]  = __ldg(Cn + HW + p);
        m1v[k] = __ldg(M1n + p);
        m2v[k] = __ldg(M2n + p);
    }

    // ── wait for staged data (acquire) ──
    {
        uint32_t done;
        asm volatile(
            "{\n\t"
            ".reg .pred p;\n\t"
            "mbarrier.try_wait.parity.acquire.cta.shared::cta.b64 p, [%1], 0;\n\t"
            "selp.b32 %0, 1, 0, p;\n\t"
            "}"
            : "=r"(done) : "r"(mbar) : "memory");
        if (!done) {
            asm volatile(
                "{\n\t"
                ".reg .pred P1;\n\t"
                "WL_%=:\n\t"
                "mbarrier.try_wait.parity.acquire.cta.shared::cta.b64 P1, [%0], 0, 0x989680;\n\t"
                "@P1 bra.uni WD_%=;\n\t"
                "bra.uni WL_%=;\n\t"
                "WD_%=:\n\t"
                "}"
                :: "r"(mbar) : "memory");
        }
    }

    float acc[3][PXT];
    #pragma unroll
    for (int c = 0; c < 3; c++)
        #pragma unroll
        for (int k = 0; k < PXT; k++) acc[c][k] = 0.0f;

    #pragma unroll
    for (int k = 0; k < PXT; k++) {
        int r = r0 + rsub + k * ROWSUB;
        float fr = (float)r, fc = (float)col;

        #pragma unroll
        for (int img = 0; img < 2; img++) {
            float s = (img == 0) ? 1.0f : -1.0f;
            float m = (img == 0) ? m1v[k] : m2v[k];
            const float* gb = (img == 0) ? b1 : b2;
            const float* spp = sp + img * 3 * PLANE_W;

            float x = fr + s * cx[k];
            float y = fc + s * cy[k];
            x = fminf(fmaxf(x, 0.001f), (float)IMG_D - 1.001f);
            y = fminf(fmaxf(y, 0.001f), (float)IMG_D - 1.001f);

            int ixf = __float2int_rd(x);
            int ixc = __float2int_ru(x);
            int iyf = __float2int_rd(y);
            int iyc = __float2int_ru(y);

            float wxf = 1.0f - (x - (float)ixf);
            float wxc = 1.0f - ((float)ixc - x);
            float wyf = 1.0f - (y - (float)iyf);
            float wyc = 1.0f - ((float)iyc - y);

            float w00 = wxf * wyf;
            float w10 = wxc * wyf;
            float w01 = wxf * wyc;
            float w11 = wxc * wyc;

            int rf = ixf - wl;
            int rc = ixc - wl;
            bool ok = ((unsigned)rf < (unsigned)wc) &
                      ((unsigned)rc < (unsigned)wc);

            float v00[3], v10[3], v01[3], v11[3];
            if (ok) {
                const float* smf = spp + rf * IMG_D;
                const float* smc = spp + rc * IMG_D;
                #pragma unroll
                for (int c = 0; c < 3; c++) {
                    v00[c] = smf[c * PLANE_W + iyf];
                    v01[c] = smf[c * PLANE_W + iyc];
                    v10[c] = smc[c * PLANE_W + iyf];
                    v11[c] = smc[c * PLANE_W + iyc];
                }
            } else {
                #pragma unroll
                for (int c = 0; c < 3; c++) {
                    const float* gf = gb + c * HW + ixf * IMG_D;
                    const float* gc = gb + c * HW + ixc * IMG_D;
                    v00[c] = __ldg(gf + iyf);
                    v01[c] = __ldg(gf + iyc);
                    v10[c] = __ldg(gc + iyf);
                    v11[c] = __ldg(gc + iyc);
                }
            }

            #pragma unroll
            for (int c = 0; c < 3; c++) {
                float sv = w00 * v00[c];
                sv += w10 * v10[c];
                sv += w01 * v01[c];
                sv += w11 * v11[c];
                acc[c][k] += m * sv;
            }
        }
    }

    float* outn = out + (size_t)n * 3 * HW;
    #pragma unroll
    for (int c = 0; c < 3; c++) {
        float* op = outn + c * HW + col;
        #pragma unroll
        for (int k = 0; k < PXT; k++)
            op[(r0 + rsub + k * ROWSUB) * IMG_D] = acc[c][k];
    }
}

extern "C" void kernel_launch(void* const* d_in, const int* in_sizes, int n_in,
                              void* d_out, int out_size)
{
    const float* im1 = (const float*)d_in[0];
    const float* im2 = (const float*)d_in[1];
    const float* C   = (const float*)d_in[2];
    const float* M1  = (const float*)d_in[3];
    const float* M2  = (const float*)d_in[4];
    float* out = (float*)d_out;

    cudaFuncSetAttribute(view_morph10_kernel,
                         cudaFuncAttributeMaxDynamicSharedMemorySize,
                         SMEM_BYTES);

    int blocks = NBATCH * TILES_PER_IMG;  // 1792
    view_morph10_kernel<<<blocks, TPB, SMEM_BYTES>>>(im1, im2, C, M1, M2, out);
}

// round 11
// speedup vs baseline: 1.3906x; 1.0573x over previous
#include <cuda_runtime.h>
#include <cstdint>

#define IMG_D 224
#define HW (IMG_D * IMG_D)
#define NBATCH 64

#define R_TILE 8
#define HALO 4
#define WMAX (R_TILE + 2 * HALO)        // 16 rows staged
#define TILES_PER_IMG (IMG_D / R_TILE)  // 28
#define TPB 448                         // 2 sub-rows x 224 cols
#define ROWSUB 2
#define PXT (R_TILE / ROWSUB)           // 4 pixels per thread
#define PLANE_W (WMAX * IMG_D)          // 3584 floats
#define PLANE_BYTES (PLANE_W * 4)       // 14336 B
#define SMEM_BYTES (6 * PLANE_BYTES)    // 86016 B -> 2 blocks/SM

// R6 structure with split-image staging: im1's 3 plane windows signal
// mbar0, im2's signal mbar1. The img-OUTER loop computes all im1
// contributions as soon as its 43KB lands, hiding im2's TMA latency
// behind im1's compute (fill exposure at block start/wave boundaries
// was the last addressable overhead). Per-element arithmetic order is
// unchanged (acc = m1-term, then += m2-term) -> bit-identical result.
__global__ __launch_bounds__(TPB)
void view_morph11_kernel(
    const float* __restrict__ im1,
    const float* __restrict__ im2,
    const float* __restrict__ C,
    const float* __restrict__ M1,
    const float* __restrict__ M2,
    float* __restrict__ out)
{
    extern __shared__ float sp[];
    __shared__ alignas(8) uint64_t mbar_storage[2];

    int blk = blockIdx.x;
    int n = blk / TILES_PER_IMG;
    int tile = blk - n * TILES_PER_IMG;
    int r0 = tile * R_TILE;

    int wl = max(0, r0 - HALO);
    int wh = min(IMG_D - 1, r0 + R_TILE - 1 + HALO);
    int wc = wh - wl + 1;

    int tid = threadIdx.x;
    int col = tid % IMG_D;
    int rsub = tid / IMG_D;

    const float* b1 = im1 + (size_t)n * 3 * HW;
    const float* b2 = im2 + (size_t)n * 3 * HW;

    uint32_t mbar0 = (uint32_t)__cvta_generic_to_shared(&mbar_storage[0]);
    uint32_t mbar1 = (uint32_t)__cvta_generic_to_shared(&mbar_storage[1]);
    uint32_t spb0  = (uint32_t)__cvta_generic_to_shared(sp);

    if (tid == 0) {
        asm volatile("mbarrier.init.shared.b64 [%0], 1;" :: "r"(mbar0) : "memory");
        asm volatile("mbarrier.init.shared.b64 [%0], 1;" :: "r"(mbar1) : "memory");
    }
    __syncthreads();

    if (tid == 0) {
        uint32_t copy_bytes = (uint32_t)(wc * IMG_D * 4);
        asm volatile("mbarrier.arrive.expect_tx.shared.b64 _, [%0], %1;"
                     :: "r"(mbar0), "r"(copy_bytes * 3) : "memory");
        asm volatile("mbarrier.arrive.expect_tx.shared.b64 _, [%0], %1;"
                     :: "r"(mbar1), "r"(copy_bytes * 3) : "memory");
        #pragma unroll
        for (int pl = 0; pl < 3; pl++) {     // im1 planes first -> mbar0
            const float* src = b1 + pl * HW + wl * IMG_D;
            asm volatile(
                "cp.async.bulk.shared::cta.global.mbarrier::complete_tx::bytes"
                " [%0], [%1], %2, [%3];"
                :: "r"(spb0 + pl * PLANE_BYTES), "l"(src),
                   "r"(copy_bytes), "r"(mbar0) : "memory");
        }
        #pragma unroll
        for (int pl = 0; pl < 3; pl++) {     // im2 planes -> mbar1
            const float* src = b2 + pl * HW + wl * IMG_D;
            asm volatile(
                "cp.async.bulk.shared::cta.global.mbarrier::complete_tx::bytes"
                " [%0], [%1], %2, [%3];"
                :: "r"(spb0 + (pl + 3) * PLANE_BYTES), "l"(src),
                   "r"(copy_bytes), "r"(mbar1) : "memory");
        }
    }

    // ── prefetch C/M while TMA runs ──
    const float* Cn  = C  + (size_t)n * 2 * HW;
    const float* M1n = M1 + (size_t)n * HW;
    const float* M2n = M2 + (size_t)n * HW;

    float cx[PXT], cy[PXT], m1v[PXT], m2v[PXT];
    #pragma unroll
    for (int k = 0; k < PXT; k++) {
        int r = r0 + rsub + k * ROWSUB;
        int p = r * IMG_D + col;
        cx[k]  = __ldg(Cn + p);
        cy[k]  = __ldg(Cn + HW + p);
        m1v[k] = __ldg(M1n + p);
        m2v[k] = __ldg(M2n + p);
    }

    float acc[3][PXT];
    #pragma unroll
    for (int c = 0; c < 3; c++)
        #pragma unroll
        for (int k = 0; k < PXT; k++) acc[c][k] = 0.0f;

    #pragma unroll
    for (int img = 0; img < 2; img++) {
        // wait for this image's 3 staged planes (acquire)
        uint32_t mbar = (img == 0) ? mbar0 : mbar1;
        {
            uint32_t done;
            asm volatile(
                "{\n\t"
                ".reg .pred p;\n\t"
                "mbarrier.try_wait.parity.acquire.cta.shared::cta.b64 p, [%1], 0;\n\t"
                "selp.b32 %0, 1, 0, p;\n\t"
                "}"
                : "=r"(done) : "r"(mbar) : "memory");
            if (!done) {
                asm volatile(
                    "{\n\t"
                    ".reg .pred P1;\n\t"
                    "WL_%=:\n\t"
                    "mbarrier.try_wait.parity.acquire.cta.shared::cta.b64 P1, [%0], 0, 0x989680;\n\t"
                    "@P1 bra.uni WD_%=;\n\t"
                    "bra.uni WL_%=;\n\t"
                    "WD_%=:\n\t"
                    "}"
                    :: "r"(mbar) : "memory");
            }
        }

        float s = (img == 0) ? 1.0f : -1.0f;
        const float* gb = (img == 0) ? b1 : b2;
        const float* spp = sp + img * 3 * PLANE_W;

        #pragma unroll
        for (int k = 0; k < PXT; k++) {
            int r = r0 + rsub + k * ROWSUB;
            float fr = (float)r, fc = (float)col;
            float m = (img == 0) ? m1v[k] : m2v[k];

            float x = fr + s * cx[k];
            float y = fc + s * cy[k];
            x = fminf(fmaxf(x, 0.001f), (float)IMG_D - 1.001f);
            y = fminf(fmaxf(y, 0.001f), (float)IMG_D - 1.001f);

            int ixf = __float2int_rd(x);
            int ixc = __float2int_ru(x);
            int iyf = __float2int_rd(y);
            int iyc = __float2int_ru(y);

            float wxf = 1.0f - (x - (float)ixf);
            float wxc = 1.0f - ((float)ixc - x);
            float wyf = 1.0f - (y - (float)iyf);
            float wyc = 1.0f - ((float)iyc - y);

            float w00 = wxf * wyf;
            float w10 = wxc * wyf;
            float w01 = wxf * wyc;
            float w11 = wxc * wyc;

            int rf = ixf - wl;
            int rc = ixc - wl;
            bool ok = ((unsigned)rf < (unsigned)wc) &
                      ((unsigned)rc < (unsigned)wc);

            float v00[3], v10[3], v01[3], v11[3];
            if (ok) {
                const float* smf = spp + rf * IMG_D;
                const float* smc = spp + rc * IMG_D;
                #pragma unroll
                for (int c = 0; c < 3; c++) {
                    v00[c] = smf[c * PLANE_W + iyf];
                    v01[c] = smf[c * PLANE_W + iyc];
                    v10[c] = smc[c * PLANE_W + iyf];
                    v11[c] = smc[c * PLANE_W + iyc];
                }
            } else {
                #pragma unroll
                for (int c = 0; c < 3; c++) {
                    const float* gf = gb + c * HW + ixf * IMG_D;
                    const float* gc = gb + c * HW + ixc * IMG_D;
                    v00[c] = __ldg(gf + iyf);
                    v01[c] = __ldg(gf + iyc);
                    v10[c] = __ldg(gc + iyf);
                    v11[c] = __ldg(gc + iyc);
                }
            }

            #pragma unroll
            for (int c = 0; c < 3; c++) {
                float sv = w00 * v00[c];
                sv += w10 * v10[c];
                sv += w01 * v01[c];
                sv += w11 * v11[c];
                acc[c][k] += m * sv;
            }
        }
    }

    float* outn = out + (size_t)n * 3 * HW;
    #pragma unroll
    for (int c = 0; c < 3; c++) {
        float* op = outn + c * HW + (r0 + rsub) * IMG_D + col;
        #pragma unroll
        for (int k = 0; k < PXT; k++)
            op[k * ROWSUB * IMG_D] = acc[c][k];
    }
}

extern "C" void kernel_launch(void* const* d_in, const int* in_sizes, int n_in,
                              void* d_out, int out_size)
{
    const float* im1 = (const float*)d_in[0];
    const float* im2 = (const float*)d_in[1];
    const float* C   = (const float*)d_in[2];
    const float* M1  = (const float*)d_in[3];
    const float* M2  = (const float*)d_in[4];
    float* out = (float*)d_out;

    cudaFuncSetAttribute(view_morph11_kernel,
                         cudaFuncAttributeMaxDynamicSharedMemorySize,
                         SMEM_BYTES);

    int blocks = NBATCH * TILES_PER_IMG;  // 1792
    view_morph11_kernel<<<blocks, TPB, SMEM_BYTES>>>(im1, im2, C, M1, M2, out);
}